// round 13
// baseline (speedup 1.0000x reference)
#include <cuda_runtime.h>
#include <cuda_fp16.h>

// QConv2d: 3x3 conv, B=16, C=32, N=64, H=W=56, stride 1, pad 1.
// Exact per-k fp16 (E5M10) requantized accumulation (bit-identical path):
//   p   = fp16(fp32(a * w))  -> FMUL.rn + cvt.rn.f16x2.f32 (packs 2 n-lanes)
//   acc = fp16(acc + p)      -> HADD2
// k order = c*9 + i*3 + j, matching lax.scan order.
//
// R13 = R12 geometry fixed: tile = 2 rows x 16 n (grid 1792, depth 4.04 at
// conc 444 -> small straggler tail), warp = 8 n-pairs x 4 px-groups, thread
// = 4 px x 1 n-pair. R12's bug: np = lane&15 addressed 32 channels inside a
// 16-channel tile (OOB weights + output overlap).

#define TB 224

#define ROWP 60                            // padded input row (floats)
#define NROWS 4                            // 2 output rows + halo
#define SIN_FLOATS (32 * NROWS * ROWP)     // 7680  -> 30720 B
#define SW_FLOATS  (288 * 16)              // 4608  -> 18432 B
#define SMEM_USED  ((SIN_FLOATS + SW_FLOATS) * 4)   // 49152
#define SMEM_BYTES 58368                   // padded so occupancy = 3 CTAs/SM

__device__ __forceinline__ __half2 cvt_pair(float n0, float n1) {
    unsigned h;
    // cvt.rn.f16x2.f32 d, a, b : a -> upper half, b -> lower half
    asm("cvt.rn.f16x2.f32 %0, %1, %2;" : "=r"(h) : "f"(n1), "f"(n0));
    return *reinterpret_cast<__half2*>(&h);
}

__global__ void __launch_bounds__(TB, 3) qconv2d_kernel(
    const float* __restrict__ x,      // [16][32][56][56]
    const float* __restrict__ w,      // [64][32][3][3] = [64][288]
    const float* __restrict__ bias,   // [64]
    float* __restrict__ out)          // [16][64][56][56]
{
    extern __shared__ float sm[];
    float* sin = sm;                      // [c][r(4)][ROWP]
    float* sw  = sm + SIN_FLOATS;         // [k=288][nc=16], fp16-valued fp32

    const int yp  = blockIdx.x;       // row pair 0..27 -> rows 2*yp, 2*yp+1
    const int b   = blockIdx.y;       // batch 0..15
    const int nq  = blockIdx.z;       // n quarter 0..3 -> n = 16*nq .. +15
    const int tid = threadIdx.x;
    const int y0  = 2 * yp;

    // ---- weights for this n-quarter: coalesced read, transpose to [k][nc] ----
    for (int idx = tid; idx < 16 * 288; idx += TB) {
        int nc = idx / 288;
        int k  = idx % 288;
        sw[k * 16 + nc] = __half2float(__float2half_rn(w[(nq * 16 + nc) * 288 + k]));
    }

    // ---- input rows y0-1..y0+2, 32 ch, padded rows of 60 (x offset by 1) ----
    const float* xb = x + (size_t)b * 32 * 56 * 56;
    for (int idx = tid; idx < SIN_FLOATS; idx += TB) {
        int c   = idx / (NROWS * ROWP);
        int rr  = idx % (NROWS * ROWP);
        int r   = rr / ROWP;
        int xs  = rr % ROWP;
        int yg  = y0 - 1 + r;
        int xg  = xs - 1;
        float v = 0.0f;
        if (yg >= 0 && yg < 56 && xg >= 0 && xg < 56)
            v = xb[(c * 56 + yg) * 56 + xg];
        sin[idx] = v;
    }
    __syncthreads();

    const int lane = tid & 31;
    const int wrp  = tid >> 5;            // 0..6
    const int np   = lane & 7;            // n-pair within quarter (0..7)
    const int h    = lane >> 3;           // px group slot 0..3
    const int grp  = wrp * 4 + h;         // 0..27
    const int row  = grp / 14;            // 0..1 (output row within pair)
    const int x0   = (grp % 14) * 4;      // output x base, 4 px per thread

    __half2 acc[4];
    #pragma unroll
    for (int p = 0; p < 4; ++p) acc[p] = __float2half2_rn(0.0f);

    const float* swt = sw + 2 * np;
    const float* ab  = sin + row * ROWP + x0;   // 16B aligned

    #pragma unroll 2
    for (int c = 0; c < 32; ++c) {
        #pragma unroll
        for (int i = 0; i < 3; ++i) {
            const float* ar = ab + (c * NROWS + i) * ROWP;
            float4 a03 = *reinterpret_cast<const float4*>(ar);       // xs x0..x0+3
            float2 a45 = *reinterpret_cast<const float2*>(ar + 4);   // xs x0+4,5
            float av[6] = { a03.x, a03.y, a03.z, a03.w, a45.x, a45.y };

            const float* wr = swt + (c * 9 + i * 3) * 16;
            float2 w0 = *reinterpret_cast<const float2*>(wr);        // j=0
            float2 w1 = *reinterpret_cast<const float2*>(wr + 16);   // j=1
            float2 w2 = *reinterpret_cast<const float2*>(wr + 32);   // j=2

            #pragma unroll
            for (int p = 0; p < 4; ++p)
                acc[p] = __hadd2(acc[p], cvt_pair(av[p] * w0.x, av[p] * w0.y));
            #pragma unroll
            for (int p = 0; p < 4; ++p)
                acc[p] = __hadd2(acc[p], cvt_pair(av[p + 1] * w1.x, av[p + 1] * w1.y));
            #pragma unroll
            for (int p = 0; p < 4; ++p)
                acc[p] = __hadd2(acc[p], cvt_pair(av[p + 2] * w2.x, av[p + 2] * w2.y));
        }
    }

    // ---- epilogue: out = fp32(fp16(acc + fp16(bias))) ----
    const int n0 = nq * 16 + 2 * np;
    __half2 qb = __halves2half2(__float2half_rn(bias[n0]),
                                __float2half_rn(bias[n0 + 1]));

    float o0v[4], o1v[4];
    #pragma unroll
    for (int p = 0; p < 4; ++p) {
        __half2 r = __hadd2(acc[p], qb);
        o0v[p] = __low2float(r);
        o1v[p] = __high2float(r);
    }

    const int y = y0 + row;
    size_t o0 = (((size_t)b * 64 + n0) * 56 + y) * 56 + x0;
    size_t o1 = (((size_t)b * 64 + n0 + 1) * 56 + y) * 56 + x0;
    *reinterpret_cast<float4*>(out + o0) = make_float4(o0v[0], o0v[1], o0v[2], o0v[3]);
    *reinterpret_cast<float4*>(out + o1) = make_float4(o1v[0], o1v[1], o1v[2], o1v[3]);
}

extern "C" void kernel_launch(void* const* d_in, const int* in_sizes, int n_in,
                              void* d_out, int out_size)
{
    const float* x    = (const float*)d_in[0];
    const float* w    = (const float*)d_in[1];
    const float* bias = (const float*)d_in[2];
    float* out = (float*)d_out;

    cudaFuncSetAttribute(qconv2d_kernel,
                         cudaFuncAttributeMaxDynamicSharedMemorySize,
                         SMEM_BYTES);

    dim3 grid(28, 16, 4);   // (row pair, batch, n quarter) = 1792 CTAs
    qconv2d_kernel<<<grid, TB, SMEM_BYTES>>>(x, w, bias, out);
}

// round 14
// speedup vs baseline: 1.0997x; 1.0997x over previous
#include <cuda_runtime.h>
#include <cuda_fp16.h>

// QConv2d: 3x3 conv, B=16, C=32, N=64, H=W=56, stride 1, pad 1.
// Exact per-k fp16 (E5M10) requantized accumulation (bit-identical path):
//   p   = fp16(fp32(a * w))  -> FMUL.rn + cvt.rn.f16x2.f32 (packs 2 n-lanes)
//   acc = fp16(acc + p)      -> HADD2
// k order = c*9 + i*3 + j, matching lax.scan order.
//
// R14 = R8 frame (tile 4 rows x 16 n, TB 224, 3 CTAs/SM, 8 px/thread) with
// overhead slots squeezed: no av[] staging array, named accumulators,
// c-loop unroll 4 so all LDS collapse to [Rbase + const] addressing.

#define TB 224

#define ROWP 60                            // padded input row (floats)
#define NROWS 6                            // 4 output rows + halo
#define SIN_FLOATS (32 * NROWS * ROWP)     // 11520 -> 46080 B
#define SW_FLOATS  (288 * 16)              // 4608  -> 18432 B
#define SMEM_BYTES ((SIN_FLOATS + SW_FLOATS) * 4)   // 64512 -> 3 CTAs/SM

__device__ __forceinline__ __half2 cvt_pair(float n0, float n1) {
    unsigned h;
    // cvt.rn.f16x2.f32 d, a, b : a -> upper half, b -> lower half
    asm("cvt.rn.f16x2.f32 %0, %1, %2;" : "=r"(h) : "f"(n1), "f"(n0));
    return *reinterpret_cast<__half2*>(&h);
}

__global__ void __launch_bounds__(TB, 3) qconv2d_kernel(
    const float* __restrict__ x,      // [16][32][56][56]
    const float* __restrict__ w,      // [64][32][3][3] = [64][288]
    const float* __restrict__ bias,   // [64]
    float* __restrict__ out)          // [16][64][56][56]
{
    extern __shared__ float sm[];
    float* sin = sm;                      // [c][r(6)][ROWP]
    float* sw  = sm + SIN_FLOATS;         // [k=288][nc=16], fp16-valued fp32

    const int yq  = blockIdx.x;       // row quad 0..13 -> rows 4*yq .. 4*yq+3
    const int b   = blockIdx.y;       // batch 0..15
    const int nq  = blockIdx.z;       // n quarter 0..3 -> n = 16*nq .. +15
    const int tid = threadIdx.x;
    const int y0  = 4 * yq;

    // ---- weights for this n-quarter: coalesced read, transpose to [k][nc] ----
    for (int idx = tid; idx < 16 * 288; idx += TB) {
        int nc = idx / 288;
        int k  = idx % 288;
        sw[k * 16 + nc] = __half2float(__float2half_rn(w[(nq * 16 + nc) * 288 + k]));
    }

    // ---- input rows y0-1..y0+4, 32 ch, padded rows of 60 (x offset by 1) ----
    const float* xb = x + (size_t)b * 32 * 56 * 56;
    for (int idx = tid; idx < SIN_FLOATS; idx += TB) {
        int c   = idx / (NROWS * ROWP);
        int rr  = idx % (NROWS * ROWP);
        int r   = rr / ROWP;
        int xs  = rr % ROWP;
        int yg  = y0 - 1 + r;
        int xg  = xs - 1;
        float v = 0.0f;
        if (yg >= 0 && yg < 56 && xg >= 0 && xg < 56)
            v = xb[(c * 56 + yg) * 56 + xg];
        sin[idx] = v;
    }
    __syncthreads();

    const int lane = tid & 31;
    const int wrp  = tid >> 5;            // 0..6
    const int np   = lane & 7;            // n-pair within quarter (0..7)
    const int h    = lane >> 3;           // px group slot 0..3
    const int grp  = wrp * 4 + h;         // 0..27
    const int row  = grp / 7;             // 0..3 (output row within quad)
    const int x0   = (grp % 7) * 8;       // output x base, 8 px per thread

    __half2 acc0 = __float2half2_rn(0.0f);
    __half2 acc1 = acc0, acc2 = acc0, acc3 = acc0;
    __half2 acc4 = acc0, acc5 = acc0, acc6 = acc0, acc7 = acc0;

    const float* swt = sw + 2 * np;              // weight pair base
    const float* ab  = sin + row * ROWP + x0;    // 16B aligned

    #pragma unroll 4
    for (int c = 0; c < 32; ++c) {
        #pragma unroll
        for (int i = 0; i < 3; ++i) {
            const float* ar = ab + (c * NROWS + i) * ROWP;
            const float4 A = *reinterpret_cast<const float4*>(ar);       // a0..a3
            const float4 B = *reinterpret_cast<const float4*>(ar + 4);   // a4..a7
            const float2 C = *reinterpret_cast<const float2*>(ar + 8);   // a8,a9

            const float* wr = swt + (c * 9 + i * 3) * 16;
            const float2 w0 = *reinterpret_cast<const float2*>(wr);       // j=0
            const float2 w1 = *reinterpret_cast<const float2*>(wr + 16);  // j=1
            const float2 w2 = *reinterpret_cast<const float2*>(wr + 32);  // j=2

            // j = 0 : px p uses a_p
            acc0 = __hadd2(acc0, cvt_pair(A.x * w0.x, A.x * w0.y));
            acc1 = __hadd2(acc1, cvt_pair(A.y * w0.x, A.y * w0.y));
            acc2 = __hadd2(acc2, cvt_pair(A.z * w0.x, A.z * w0.y));
            acc3 = __hadd2(acc3, cvt_pair(A.w * w0.x, A.w * w0.y));
            acc4 = __hadd2(acc4, cvt_pair(B.x * w0.x, B.x * w0.y));
            acc5 = __hadd2(acc5, cvt_pair(B.y * w0.x, B.y * w0.y));
            acc6 = __hadd2(acc6, cvt_pair(B.z * w0.x, B.z * w0.y));
            acc7 = __hadd2(acc7, cvt_pair(B.w * w0.x, B.w * w0.y));
            // j = 1 : px p uses a_{p+1}
            acc0 = __hadd2(acc0, cvt_pair(A.y * w1.x, A.y * w1.y));
            acc1 = __hadd2(acc1, cvt_pair(A.z * w1.x, A.z * w1.y));
            acc2 = __hadd2(acc2, cvt_pair(A.w * w1.x, A.w * w1.y));
            acc3 = __hadd2(acc3, cvt_pair(B.x * w1.x, B.x * w1.y));
            acc4 = __hadd2(acc4, cvt_pair(B.y * w1.x, B.y * w1.y));
            acc5 = __hadd2(acc5, cvt_pair(B.z * w1.x, B.z * w1.y));
            acc6 = __hadd2(acc6, cvt_pair(B.w * w1.x, B.w * w1.y));
            acc7 = __hadd2(acc7, cvt_pair(C.x * w1.x, C.x * w1.y));
            // j = 2 : px p uses a_{p+2}
            acc0 = __hadd2(acc0, cvt_pair(A.z * w2.x, A.z * w2.y));
            acc1 = __hadd2(acc1, cvt_pair(A.w * w2.x, A.w * w2.y));
            acc2 = __hadd2(acc2, cvt_pair(B.x * w2.x, B.x * w2.y));
            acc3 = __hadd2(acc3, cvt_pair(B.y * w2.x, B.y * w2.y));
            acc4 = __hadd2(acc4, cvt_pair(B.z * w2.x, B.z * w2.y));
            acc5 = __hadd2(acc5, cvt_pair(B.w * w2.x, B.w * w2.y));
            acc6 = __hadd2(acc6, cvt_pair(C.x * w2.x, C.x * w2.y));
            acc7 = __hadd2(acc7, cvt_pair(C.y * w2.x, C.y * w2.y));
        }
    }

    // ---- epilogue: out = fp32(fp16(acc + fp16(bias))) ----
    const int n0 = nq * 16 + 2 * np;
    __half2 qb = __halves2half2(__float2half_rn(bias[n0]),
                                __float2half_rn(bias[n0 + 1]));

    __half2 r0 = __hadd2(acc0, qb), r1 = __hadd2(acc1, qb);
    __half2 r2 = __hadd2(acc2, qb), r3 = __hadd2(acc3, qb);
    __half2 r4 = __hadd2(acc4, qb), r5 = __hadd2(acc5, qb);
    __half2 r6 = __hadd2(acc6, qb), r7 = __hadd2(acc7, qb);

    const int y = y0 + row;
    size_t o0 = (((size_t)b * 64 + n0) * 56 + y) * 56 + x0;
    size_t o1 = (((size_t)b * 64 + n0 + 1) * 56 + y) * 56 + x0;

    *reinterpret_cast<float4*>(out + o0) =
        make_float4(__low2float(r0), __low2float(r1), __low2float(r2), __low2float(r3));
    *reinterpret_cast<float4*>(out + o0 + 4) =
        make_float4(__low2float(r4), __low2float(r5), __low2float(r6), __low2float(r7));
    *reinterpret_cast<float4*>(out + o1) =
        make_float4(__high2float(r0), __high2float(r1), __high2float(r2), __high2float(r3));
    *reinterpret_cast<float4*>(out + o1 + 4) =
        make_float4(__high2float(r4), __high2float(r5), __high2float(r6), __high2float(r7));
}

extern "C" void kernel_launch(void* const* d_in, const int* in_sizes, int n_in,
                              void* d_out, int out_size)
{
    const float* x    = (const float*)d_in[0];
    const float* w    = (const float*)d_in[1];
    const float* bias = (const float*)d_in[2];
    float* out = (float*)d_out;

    cudaFuncSetAttribute(qconv2d_kernel,
                         cudaFuncAttributeMaxDynamicSharedMemorySize,
                         SMEM_BYTES);

    dim3 grid(14, 16, 4);   // (row quad, batch, n quarter)
    qconv2d_kernel<<<grid, TB, SMEM_BYTES>>>(x, w, bias, out);
}